// round 1
// baseline (speedup 1.0000x reference)
#include <cuda_runtime.h>
#include <cuda_bf16.h>
#include <mma.h>
#include <math.h>

using namespace nvcuda;

#define BATCH 2048
#define SEQ   80
#define UNITS 512
#define EMB   100
#define EMBP  128
#define BT    (BATCH*SEQ)

#define BM 128
#define BN 64
#define BK 32
#define THREADS 256

// ---------------- persistent device scratch (allocation-free rule) ----------------
__device__ __nv_bfloat16 g_X[(size_t)BT * EMBP];    // layer-1 input, zero-padded K=128
__device__ float         g_Z[(size_t)BT * UNITS];   // per-layer input-GEMM result
__device__ __nv_bfloat16 g_H[(size_t)BT * UNITS];   // per-layer hidden states (bf16)
__device__ __nv_bfloat16 g_W1p[EMBP * UNITS];       // W1 padded to [128][512]
__device__ __nv_bfloat16 g_W[3][UNITS * UNITS];     // W2..W4 bf16
__device__ __nv_bfloat16 g_U[4][UNITS * UNITS];     // U1..U4 bf16

// ---------------- prep kernels ----------------
__global__ void embed_kernel(const int* __restrict__ tokens, const float* __restrict__ emb) {
    size_t idx = (size_t)blockIdx.x * blockDim.x + threadIdx.x;
    if (idx >= (size_t)BT * EMBP) return;
    size_t row = idx >> 7;          // b*SEQ + t
    int col = (int)(idx & 127);
    int tok = tokens[row];
    float v = (col < EMB) ? emb[(size_t)tok * EMB + col] : 0.f;
    g_X[idx] = __float2bfloat16(v);
}

__global__ void prep_w1(const float* __restrict__ W1) {
    int idx = blockIdx.x * blockDim.x + threadIdx.x;
    if (idx >= EMBP * UNITS) return;
    int k = idx >> 9, n = idx & 511;
    g_W1p[idx] = __float2bfloat16(k < EMB ? W1[k * UNITS + n] : 0.f);
}

__global__ void prep_w(const float* __restrict__ src, int l) {
    int idx = blockIdx.x * blockDim.x + threadIdx.x;
    if (idx >= UNITS * UNITS) return;
    g_W[l][idx] = __float2bfloat16(src[idx]);
}

__global__ void prep_u(const float* __restrict__ src, int l) {
    int idx = blockIdx.x * blockDim.x + threadIdx.x;
    if (idx >= UNITS * UNITS) return;
    g_U[l][idx] = __float2bfloat16(src[idx]);
}

// ---------------- bulk input GEMM: g_Z = A @ W  (no epilogue; bias folded into scan) ----------------
__global__ __launch_bounds__(THREADS) void gemm_in(int layer) {
    const __nv_bfloat16* A;
    const __nv_bfloat16* Bm;
    int K;
    if (layer == 0) { A = g_X; K = EMBP;  Bm = g_W1p; }
    else            { A = g_H; K = UNITS; Bm = g_W[layer - 1]; }

    const int n0 = blockIdx.x * BN;
    const int m0 = blockIdx.y * BM;

    __shared__ __align__(16) __nv_bfloat16 sA[BM * (BK + 8)];
    __shared__ __align__(16) __nv_bfloat16 sB[BK * (BN + 8)];

    const int tid = threadIdx.x;
    const int wid = tid >> 5;
    const int wm = wid & 3, wn = wid >> 2;

    wmma::fragment<wmma::accumulator, 16, 16, 16, float> acc[2][2];
    #pragma unroll
    for (int i = 0; i < 2; i++)
        #pragma unroll
        for (int j = 0; j < 2; j++) wmma::fill_fragment(acc[i][j], 0.f);

    for (int k0 = 0; k0 < K; k0 += BK) {
        for (int i = tid; i < BM * (BK / 8); i += THREADS) {
            int r = i >> 2, c = i & 3;
            *(uint4*)&sA[r * (BK + 8) + c * 8] =
                *(const uint4*)(A + (size_t)(m0 + r) * K + k0 + c * 8);
        }
        {
            int r = tid >> 3, c = tid & 7;
            *(uint4*)&sB[r * (BN + 8) + c * 8] =
                *(const uint4*)(Bm + (size_t)(k0 + r) * UNITS + n0 + c * 8);
        }
        __syncthreads();
        #pragma unroll
        for (int kk = 0; kk < BK; kk += 16) {
            wmma::fragment<wmma::matrix_a, 16, 16, 16, __nv_bfloat16, wmma::row_major> af[2];
            wmma::fragment<wmma::matrix_b, 16, 16, 16, __nv_bfloat16, wmma::row_major> bf[2];
            #pragma unroll
            for (int i = 0; i < 2; i++)
                wmma::load_matrix_sync(af[i], &sA[(wm * 32 + i * 16) * (BK + 8) + kk], BK + 8);
            #pragma unroll
            for (int j = 0; j < 2; j++)
                wmma::load_matrix_sync(bf[j], &sB[kk * (BN + 8) + wn * 32 + j * 16], BN + 8);
            #pragma unroll
            for (int i = 0; i < 2; i++)
                #pragma unroll
                for (int j = 0; j < 2; j++)
                    wmma::mma_sync(acc[i][j], af[i], bf[j], acc[i][j]);
        }
        __syncthreads();
    }

    #pragma unroll
    for (int i = 0; i < 2; i++)
        #pragma unroll
        for (int j = 0; j < 2; j++)
            wmma::store_matrix_sync(
                g_Z + (size_t)(m0 + wm * 32 + i * 16) * UNITS + n0 + wn * 32 + j * 16,
                acc[i][j], UNITS, wmma::mem_row_major);
}

// ---------------- recurrent step: h_t = tanh(Z_t + h_{t-1} @ U + b) ----------------
__global__ __launch_bounds__(THREADS) void rnn_step(int layer, const float* __restrict__ bias, int t) {
    const int n0 = blockIdx.x * BN;
    const int m0 = blockIdx.y * BM;   // batch tile

    // A/B tiles and the fp32 C tile share this buffer (disjoint in time)
    __shared__ __align__(16) unsigned char smraw[BM * 68 * 4];  // 34816 B
    __nv_bfloat16* sA = (__nv_bfloat16*)smraw;                       // [128][40]
    __nv_bfloat16* sB = (__nv_bfloat16*)(smraw + BM * (BK + 8) * 2); // [32][72]
    float* sC = (float*)smraw;                                       // [128][68]

    const __nv_bfloat16* U = g_U[layer];
    const int tid = threadIdx.x;
    const int wid = tid >> 5;
    const int wm = wid & 3, wn = wid >> 2;

    wmma::fragment<wmma::accumulator, 16, 16, 16, float> acc[2][2];
    #pragma unroll
    for (int i = 0; i < 2; i++)
        #pragma unroll
        for (int j = 0; j < 2; j++) wmma::fill_fragment(acc[i][j], 0.f);

    if (t > 0) {
        const __nv_bfloat16* A = g_H + (size_t)(t - 1) * UNITS;   // row b at b*SEQ*UNITS
        const size_t aStride = (size_t)SEQ * UNITS;
        for (int k0 = 0; k0 < UNITS; k0 += BK) {
            for (int i = tid; i < BM * (BK / 8); i += THREADS) {
                int r = i >> 2, c = i & 3;
                *(uint4*)&sA[r * (BK + 8) + c * 8] =
                    *(const uint4*)(A + (size_t)(m0 + r) * aStride + k0 + c * 8);
            }
            {
                int r = tid >> 3, c = tid & 7;
                *(uint4*)&sB[r * (BN + 8) + c * 8] =
                    *(const uint4*)(U + (size_t)(k0 + r) * UNITS + n0 + c * 8);
            }
            __syncthreads();
            #pragma unroll
            for (int kk = 0; kk < BK; kk += 16) {
                wmma::fragment<wmma::matrix_a, 16, 16, 16, __nv_bfloat16, wmma::row_major> af[2];
                wmma::fragment<wmma::matrix_b, 16, 16, 16, __nv_bfloat16, wmma::row_major> bf[2];
                #pragma unroll
                for (int i = 0; i < 2; i++)
                    wmma::load_matrix_sync(af[i], &sA[(wm * 32 + i * 16) * (BK + 8) + kk], BK + 8);
                #pragma unroll
                for (int j = 0; j < 2; j++)
                    wmma::load_matrix_sync(bf[j], &sB[kk * (BN + 8) + wn * 32 + j * 16], BN + 8);
                #pragma unroll
                for (int i = 0; i < 2; i++)
                    #pragma unroll
                    for (int j = 0; j < 2; j++)
                        wmma::mma_sync(acc[i][j], af[i], bf[j], acc[i][j]);
            }
            __syncthreads();
        }
    }

    // stage accumulators to smem, then fused bias + Z + tanh epilogue
    #pragma unroll
    for (int i = 0; i < 2; i++)
        #pragma unroll
        for (int j = 0; j < 2; j++)
            wmma::store_matrix_sync(&sC[(wm * 32 + i * 16) * 68 + wn * 32 + j * 16],
                                    acc[i][j], 68, wmma::mem_row_major);
    __syncthreads();

    for (int i = tid; i < BM * BN; i += THREADS) {
        int r = i >> 6, c = i & 63;
        int b = m0 + r, n = n0 + c;
        size_t idx = ((size_t)b * SEQ + t) * UNITS + n;
        float v = tanhf(sC[r * 68 + c] + g_Z[idx] + bias[n]);
        g_H[idx] = __float2bfloat16(v);
    }
}

// ---------------- head: out = sigmoid(h_last @ Wo + bo) ----------------
__global__ void head(const float* __restrict__ Wo, const float* __restrict__ bo,
                     float* __restrict__ out) {
    int gt = blockIdx.x * blockDim.x + threadIdx.x;
    int w = gt >> 5, lane = gt & 31;
    if (w >= BATCH) return;
    const __nv_bfloat16* h = g_H + ((size_t)w * SEQ + (SEQ - 1)) * UNITS;
    float s = 0.f;
    for (int k = lane; k < UNITS; k += 32)
        s += __bfloat162float(h[k]) * Wo[k];
    #pragma unroll
    for (int o = 16; o; o >>= 1) s += __shfl_xor_sync(0xffffffffu, s, o);
    if (lane == 0) out[w] = 1.f / (1.f + expf(-(s + bo[0])));
}

// ---------------- launch ----------------
extern "C" void kernel_launch(void* const* d_in, const int* in_sizes, int n_in,
                              void* d_out, int out_size) {
    const int*   tokens = (const int*)d_in[0];
    const float* emb    = (const float*)d_in[1];
    const float* Wm[4]  = {(const float*)d_in[2],  (const float*)d_in[5],
                           (const float*)d_in[8],  (const float*)d_in[11]};
    const float* Um[4]  = {(const float*)d_in[3],  (const float*)d_in[6],
                           (const float*)d_in[9],  (const float*)d_in[12]};
    const float* bm[4]  = {(const float*)d_in[4],  (const float*)d_in[7],
                           (const float*)d_in[10], (const float*)d_in[13]};
    const float* Wo = (const float*)d_in[14];
    const float* bo = (const float*)d_in[15];
    float* out = (float*)d_out;

    embed_kernel<<<(int)(((size_t)BT * EMBP + 255) / 256), 256>>>(tokens, emb);
    prep_w1<<<(EMBP * UNITS + 255) / 256, 256>>>(Wm[0]);
    for (int l = 1; l < 4; l++)
        prep_w<<<(UNITS * UNITS + 255) / 256, 256>>>(Wm[l], l - 1);
    for (int l = 0; l < 4; l++)
        prep_u<<<(UNITS * UNITS + 255) / 256, 256>>>(Um[l], l);

    dim3 gin(UNITS / BN, BT / BM);     // (8, 1280)
    dim3 gst(UNITS / BN, BATCH / BM);  // (8, 16)
    for (int l = 0; l < 4; l++) {
        gemm_in<<<gin, THREADS>>>(l);
        for (int t = 0; t < SEQ; t++)
            rnn_step<<<gst, THREADS>>>(l, bm[l], t);
    }
    head<<<(BATCH * 32 + 255) / 256, 256>>>(Wo, bo, out);
}

// round 2
// speedup vs baseline: 1.1521x; 1.1521x over previous
#include <cuda_runtime.h>
#include <cuda_bf16.h>
#include <mma.h>
#include <math.h>

using namespace nvcuda;

#define BATCH 2048
#define SEQ   80
#define UNITS 512
#define EMB   100
#define EMBP  128
#define BT    (BATCH*SEQ)

#define BM 128
#define BN 64
#define BK 32
#define THREADS 256
#define NBLK 128                 // persistent scan grid (16 m-tiles x 8 n-tiles)

// ---------------- persistent device scratch (allocation-free rule) ----------------
__device__ __nv_bfloat16 g_X[(size_t)BT * EMBP];    // layer-1 input, zero-padded K=128
__device__ float         g_Z[(size_t)BT * UNITS];   // per-layer input-GEMM result
__device__ __nv_bfloat16 g_H[(size_t)BT * UNITS];   // per-layer hidden states (bf16)
__device__ __nv_bfloat16 g_W1p[EMBP * UNITS];       // W1 padded to [128][512]
__device__ __nv_bfloat16 g_W[3][UNITS * UNITS];     // W2..W4 bf16
__device__ __nv_bfloat16 g_U[4][UNITS * UNITS];     // U1..U4 bf16
__device__ unsigned int  g_arrive;                  // grid-barrier counter (memset per launch)

// ---------------- prep kernels ----------------
__global__ void embed_kernel(const int* __restrict__ tokens, const float* __restrict__ emb) {
    size_t idx = (size_t)blockIdx.x * blockDim.x + threadIdx.x;
    if (idx >= (size_t)BT * EMBP) return;
    size_t row = idx >> 7;
    int col = (int)(idx & 127);
    int tok = tokens[row];
    float v = (col < EMB) ? emb[(size_t)tok * EMB + col] : 0.f;
    g_X[idx] = __float2bfloat16(v);
}

__global__ void prep_w1(const float* __restrict__ W1) {
    int idx = blockIdx.x * blockDim.x + threadIdx.x;
    if (idx >= EMBP * UNITS) return;
    int k = idx >> 9, n = idx & 511;
    g_W1p[idx] = __float2bfloat16(k < EMB ? W1[k * UNITS + n] : 0.f);
}

__global__ void prep_w(const float* __restrict__ src, int l) {
    int idx = blockIdx.x * blockDim.x + threadIdx.x;
    if (idx >= UNITS * UNITS) return;
    g_W[l][idx] = __float2bfloat16(src[idx]);
}

__global__ void prep_u(const float* __restrict__ src, int l) {
    int idx = blockIdx.x * blockDim.x + threadIdx.x;
    if (idx >= UNITS * UNITS) return;
    g_U[l][idx] = __float2bfloat16(src[idx]);
}

// ---------------- bulk input GEMM: g_Z = A @ W (bias folded into scan) ----------------
__global__ __launch_bounds__(THREADS) void gemm_in(int layer) {
    const __nv_bfloat16* A;
    const __nv_bfloat16* Bm;
    int K;
    if (layer == 0) { A = g_X; K = EMBP;  Bm = g_W1p; }
    else            { A = g_H; K = UNITS; Bm = g_W[layer - 1]; }

    const int n0 = blockIdx.x * BN;
    const int m0 = blockIdx.y * BM;

    __shared__ __align__(16) __nv_bfloat16 sA[BM * (BK + 8)];
    __shared__ __align__(16) __nv_bfloat16 sB[BK * (BN + 8)];

    const int tid = threadIdx.x;
    const int wid = tid >> 5;
    const int wm = wid & 3, wn = wid >> 2;

    wmma::fragment<wmma::accumulator, 16, 16, 16, float> acc[2][2];
    #pragma unroll
    for (int i = 0; i < 2; i++)
        #pragma unroll
        for (int j = 0; j < 2; j++) wmma::fill_fragment(acc[i][j], 0.f);

    for (int k0 = 0; k0 < K; k0 += BK) {
        for (int i = tid; i < BM * (BK / 8); i += THREADS) {
            int r = i >> 2, c = i & 3;
            *(uint4*)&sA[r * (BK + 8) + c * 8] =
                *(const uint4*)(A + (size_t)(m0 + r) * K + k0 + c * 8);
        }
        {
            int r = tid >> 3, c = tid & 7;
            *(uint4*)&sB[r * (BN + 8) + c * 8] =
                *(const uint4*)(Bm + (size_t)(k0 + r) * UNITS + n0 + c * 8);
        }
        __syncthreads();
        #pragma unroll
        for (int kk = 0; kk < BK; kk += 16) {
            wmma::fragment<wmma::matrix_a, 16, 16, 16, __nv_bfloat16, wmma::row_major> af[2];
            wmma::fragment<wmma::matrix_b, 16, 16, 16, __nv_bfloat16, wmma::row_major> bf[2];
            #pragma unroll
            for (int i = 0; i < 2; i++)
                wmma::load_matrix_sync(af[i], &sA[(wm * 32 + i * 16) * (BK + 8) + kk], BK + 8);
            #pragma unroll
            for (int j = 0; j < 2; j++)
                wmma::load_matrix_sync(bf[j], &sB[kk * (BN + 8) + wn * 32 + j * 16], BN + 8);
            #pragma unroll
            for (int i = 0; i < 2; i++)
                #pragma unroll
                for (int j = 0; j < 2; j++)
                    wmma::mma_sync(acc[i][j], af[i], bf[j], acc[i][j]);
        }
        __syncthreads();
    }

    #pragma unroll
    for (int i = 0; i < 2; i++)
        #pragma unroll
        for (int j = 0; j < 2; j++)
            wmma::store_matrix_sync(
                g_Z + (size_t)(m0 + wm * 32 + i * 16) * UNITS + n0 + wn * 32 + j * 16,
                acc[i][j], UNITS, wmma::mem_row_major);
}

// ---------------- persistent scan: 80 steps, U resident in smem, grid barriers ----------------
// smem layout (dynamic):
//   sU    : [512][72]  bf16  = 73728 B   (U[:, n0:n0+64], resident all steps)
//   sA    : 2 x [128][40] bf16 = 20480 B (double-buffered h_{t-1} tile)
//   sC    : [128][68]  f32   = 34816 B   (epilogue staging)
//   sBias : [64]       f32   = 256 B
#define SMEM_SU  0
#define SMEM_SA  73728
#define SMEM_SC  94208
#define SMEM_SB  129024
#define SMEM_SCAN (129024 + 256)

__device__ __forceinline__ void grid_sync(unsigned int target) {
    __syncthreads();
    if (threadIdx.x == 0) {
        __threadfence();
        atomicAdd(&g_arrive, 1u);
        volatile unsigned int* p = &g_arrive;
        while (*p < target) { }
        __threadfence();
    }
    __syncthreads();
}

__global__ __launch_bounds__(THREADS, 1) void scan_layer(int layer,
                                                         const float* __restrict__ bias,
                                                         unsigned int barBase) {
    extern __shared__ __align__(16) unsigned char smraw[];
    __nv_bfloat16* sU = (__nv_bfloat16*)(smraw + SMEM_SU);
    __nv_bfloat16* sA = (__nv_bfloat16*)(smraw + SMEM_SA);   // two buffers of 128*40
    float*         sC = (float*)(smraw + SMEM_SC);
    float*         sBias = (float*)(smraw + SMEM_SB);

    const int tid = threadIdx.x;
    const int bid = blockIdx.x;
    const int n0 = (bid & 7) * BN;
    const int m0 = (bid >> 3) * BM;
    const int wid = tid >> 5;
    const int wm = wid & 3, wn = wid >> 2;

    // load U[:, n0:n0+64] into smem once (512 rows x 64 cols, pad to 72)
    {
        const __nv_bfloat16* U = g_U[layer];
        for (int i = tid; i < 4096; i += THREADS) {       // 4096 uint4 = 64KB
            int r = i >> 3, c = i & 7;
            *(uint4*)&sU[r * 72 + c * 8] =
                *(const uint4*)(U + (size_t)r * UNITS + n0 + c * 8);
        }
        if (tid < BN) sBias[tid] = bias[n0 + tid];
    }
    __syncthreads();

    const size_t aStride = (size_t)SEQ * UNITS;
    unsigned int tgt = barBase;

    for (int t = 0; t < SEQ; t++) {
        if (t == 0) {
            // h_0 = tanh(Z_0 + b)
            for (int i = tid; i < BM * BN; i += THREADS) {
                int r = i >> 6, c = i & 63;
                size_t idx = ((size_t)(m0 + r) * SEQ + 0) * UNITS + n0 + c;
                g_H[idx] = __float2bfloat16(tanhf(g_Z[idx] + sBias[c]));
            }
        } else {
            const __nv_bfloat16* A = g_H + (size_t)(t - 1) * UNITS;

            wmma::fragment<wmma::accumulator, 16, 16, 16, float> acc[2][2];
            #pragma unroll
            for (int i = 0; i < 2; i++)
                #pragma unroll
                for (int j = 0; j < 2; j++) wmma::fill_fragment(acc[i][j], 0.f);

            // prologue: load k0=0 tile into buf 0
            int buf = 0;
            {
                #pragma unroll
                for (int j = 0; j < 2; j++) {
                    int idx = tid + j * THREADS;          // 512 uint4 total
                    int r = idx >> 2, c = idx & 3;
                    *(uint4*)&sA[r * (BK + 8) + c * 8] =
                        *(const uint4*)(A + (size_t)(m0 + r) * aStride + c * 8);
                }
            }
            __syncthreads();

            for (int k0 = 0; k0 < UNITS; k0 += BK) {
                const bool more = (k0 + BK) < UNITS;
                uint4 pre[2];
                int pr[2], pc[2];
                if (more) {
                    #pragma unroll
                    for (int j = 0; j < 2; j++) {
                        int idx = tid + j * THREADS;
                        pr[j] = idx >> 2; pc[j] = idx & 3;
                        pre[j] = *(const uint4*)(A + (size_t)(m0 + pr[j]) * aStride
                                                 + (k0 + BK) + pc[j] * 8);
                    }
                }
                const __nv_bfloat16* sAb = sA + buf * (BM * (BK + 8));
                #pragma unroll
                for (int kk = 0; kk < BK; kk += 16) {
                    wmma::fragment<wmma::matrix_a, 16, 16, 16, __nv_bfloat16, wmma::row_major> af[2];
                    wmma::fragment<wmma::matrix_b, 16, 16, 16, __nv_bfloat16, wmma::row_major> bf[2];
                    #pragma unroll
                    for (int i = 0; i < 2; i++)
                        wmma::load_matrix_sync(af[i], &sAb[(wm * 32 + i * 16) * (BK + 8) + kk], BK + 8);
                    #pragma unroll
                    for (int j = 0; j < 2; j++)
                        wmma::load_matrix_sync(bf[j], &sU[(k0 + kk) * 72 + wn * 32 + j * 16], 72);
                    #pragma unroll
                    for (int i = 0; i < 2; i++)
                        #pragma unroll
                        for (int j = 0; j < 2; j++)
                            wmma::mma_sync(acc[i][j], af[i], bf[j], acc[i][j]);
                }
                if (more) {
                    __nv_bfloat16* sAn = sA + (buf ^ 1) * (BM * (BK + 8));
                    #pragma unroll
                    for (int j = 0; j < 2; j++)
                        *(uint4*)&sAn[pr[j] * (BK + 8) + pc[j] * 8] = pre[j];
                }
                __syncthreads();
                buf ^= 1;
            }

            // stage accumulators, fused epilogue
            #pragma unroll
            for (int i = 0; i < 2; i++)
                #pragma unroll
                for (int j = 0; j < 2; j++)
                    wmma::store_matrix_sync(&sC[(wm * 32 + i * 16) * 68 + wn * 32 + j * 16],
                                            acc[i][j], 68, wmma::mem_row_major);
            __syncthreads();

            for (int i = tid; i < BM * BN; i += THREADS) {
                int r = i >> 6, c = i & 63;
                size_t idx = ((size_t)(m0 + r) * SEQ + t) * UNITS + n0 + c;
                float v = tanhf(sC[r * 68 + c] + g_Z[idx] + sBias[c]);
                g_H[idx] = __float2bfloat16(v);
            }
        }

        if (t + 1 < SEQ) {        // no barrier after the last step
            tgt += NBLK;
            grid_sync(tgt);
        }
    }
}

// ---------------- head: out = sigmoid(h_last @ Wo + bo) ----------------
__global__ void head(const float* __restrict__ Wo, const float* __restrict__ bo,
                     float* __restrict__ out) {
    int gt = blockIdx.x * blockDim.x + threadIdx.x;
    int w = gt >> 5, lane = gt & 31;
    if (w >= BATCH) return;
    const __nv_bfloat16* h = g_H + ((size_t)w * SEQ + (SEQ - 1)) * UNITS;
    float s = 0.f;
    for (int k = lane; k < UNITS; k += 32)
        s += __bfloat162float(h[k]) * Wo[k];
    #pragma unroll
    for (int o = 16; o; o >>= 1) s += __shfl_xor_sync(0xffffffffu, s, o);
    if (lane == 0) out[w] = 1.f / (1.f + expf(-(s + bo[0])));
}

// ---------------- launch ----------------
extern "C" void kernel_launch(void* const* d_in, const int* in_sizes, int n_in,
                              void* d_out, int out_size) {
    const int*   tokens = (const int*)d_in[0];
    const float* emb    = (const float*)d_in[1];
    const float* Wm[4]  = {(const float*)d_in[2],  (const float*)d_in[5],
                           (const float*)d_in[8],  (const float*)d_in[11]};
    const float* Um[4]  = {(const float*)d_in[3],  (const float*)d_in[6],
                           (const float*)d_in[9],  (const float*)d_in[12]};
    const float* bm[4]  = {(const float*)d_in[4],  (const float*)d_in[7],
                           (const float*)d_in[10], (const float*)d_in[13]};
    const float* Wo = (const float*)d_in[14];
    const float* bo = (const float*)d_in[15];
    float* out = (float*)d_out;

    cudaFuncSetAttribute(scan_layer, cudaFuncAttributeMaxDynamicSharedMemorySize, SMEM_SCAN);

    // reset grid barrier counter for this launch
    void* barAddr = nullptr;
    cudaGetSymbolAddress(&barAddr, g_arrive);
    cudaMemsetAsync(barAddr, 0, sizeof(unsigned int));

    embed_kernel<<<(int)(((size_t)BT * EMBP + 255) / 256), 256>>>(tokens, emb);
    prep_w1<<<(EMBP * UNITS + 255) / 256, 256>>>(Wm[0]);
    for (int l = 1; l < 4; l++)
        prep_w<<<(UNITS * UNITS + 255) / 256, 256>>>(Wm[l], l - 1);
    for (int l = 0; l < 4; l++)
        prep_u<<<(UNITS * UNITS + 255) / 256, 256>>>(Um[l], l);

    dim3 gin(UNITS / BN, BT / BM);     // (8, 1280)
    for (int l = 0; l < 4; l++) {
        gemm_in<<<gin, THREADS>>>(l);
        scan_layer<<<NBLK, THREADS, SMEM_SCAN>>>(l, bm[l], (unsigned)(l * (SEQ - 1) * NBLK));
    }
    head<<<(BATCH * 32 + 255) / 256, 256>>>(Wo, bo, out);
}

// round 5
// speedup vs baseline: 2.0477x; 1.7774x over previous
#include <cuda_runtime.h>
#include <cuda_bf16.h>
#include <mma.h>
#include <math.h>
#include <cstdint>

using namespace nvcuda;

#define BATCH 2048
#define SEQ   80
#define UNITS 512
#define EMB   100
#define EMBP  128
#define BT    (BATCH*SEQ)

#define BM 128
#define BN 64
#define THREADS 512
#define NBLK 128                 // persistent scan grid (16 m-tiles x 8 n-tiles)

#define LDA 520                  // 512 + 8 pad (elements)
#define LDA0 136                 // 128 + 8 pad (layer-0 bulk A)
#define LDB 72                   // 64 + 8 pad
#define LDC 68                   // f32 epilogue staging stride

// smem byte offsets (shared by gemm_in and scan_layer)
#define SM_A    0                // A: 128 x LDA bf16 = 133120 B  (sC f32 aliases here)
#define SM_B    133120           // B: 512 x LDB bf16 = 73728 B
#define SM_BIAS 206848           // 64 f32
#define SM_TOTAL 207104

// ---------------- persistent device scratch ----------------
__device__ __nv_bfloat16 g_X[(size_t)BT * EMBP];
__device__ __nv_bfloat16 g_Z[(size_t)BT * UNITS];
__device__ __nv_bfloat16 g_H[(size_t)BT * UNITS];
__device__ __nv_bfloat16 g_W1p[EMBP * UNITS];
__device__ __nv_bfloat16 g_W[3][UNITS * UNITS];
__device__ __nv_bfloat16 g_U[4][UNITS * UNITS];
__device__ unsigned int  g_arrive;

// ---------------- prep kernels ----------------
__global__ void embed_kernel(const int* __restrict__ tokens, const float* __restrict__ emb) {
    size_t idx = (size_t)blockIdx.x * blockDim.x + threadIdx.x;
    if (idx >= (size_t)BT * EMBP) return;
    size_t row = idx >> 7;
    int col = (int)(idx & 127);
    int tok = tokens[row];
    float v = (col < EMB) ? emb[(size_t)tok * EMB + col] : 0.f;
    g_X[idx] = __float2bfloat16(v);
}

__global__ void prep_w1(const float* __restrict__ W1) {
    int idx = blockIdx.x * blockDim.x + threadIdx.x;
    if (idx >= EMBP * UNITS) return;
    int k = idx >> 9, n = idx & 511;
    g_W1p[idx] = __float2bfloat16(k < EMB ? W1[k * UNITS + n] : 0.f);
}

__global__ void prep_w(const float* __restrict__ src, int l) {
    int idx = blockIdx.x * blockDim.x + threadIdx.x;
    if (idx >= UNITS * UNITS) return;
    g_W[l][idx] = __float2bfloat16(src[idx]);
}

__global__ void prep_u(const float* __restrict__ src, int l) {
    int idx = blockIdx.x * blockDim.x + threadIdx.x;
    if (idx >= UNITS * UNITS) return;
    g_U[l][idx] = __float2bfloat16(src[idx]);
}

// ---------------- bulk input GEMM: g_Z = A @ W (bf16 out, no inner syncs) ----------------
__global__ __launch_bounds__(THREADS, 1) void gemm_in(int layer) {
    extern __shared__ __align__(16) unsigned char smraw[];
    __nv_bfloat16* sA = (__nv_bfloat16*)(smraw + SM_A);
    __nv_bfloat16* sB = (__nv_bfloat16*)(smraw + SM_B);
    float*         sC = (float*)(smraw + SM_A);      // alias after MMA

    const __nv_bfloat16* A;
    const __nv_bfloat16* Bm;
    int K, lda, nushift;
    if (layer == 0) { A = g_X; K = EMBP;  Bm = g_W1p;        lda = LDA0; nushift = 4; }
    else            { A = g_H; K = UNITS; Bm = g_W[layer-1]; lda = LDA;  nushift = 6; }

    const int n0 = blockIdx.x * BN;
    const int m0 = blockIdx.y * BM;
    const int tid = threadIdx.x;
    const int wid = tid >> 5, lane = tid & 31;
    const int wm = wid & 3, wn = wid >> 2;          // 4 x 4 warp grid; warp tile 32m x 16n

    // stage A [128 x K] and B [K x 64]
    {
        const int nu = 1 << nushift;                // uint4 per A row
        for (int i = tid; i < BM * nu; i += THREADS) {
            int r = i >> nushift, c = i & (nu - 1);
            *(uint4*)&sA[r * lda + c * 8] =
                *(const uint4*)(A + (size_t)(m0 + r) * K + c * 8);
        }
        for (int i = tid; i < K * 8; i += THREADS) {
            int r = i >> 3, c = i & 7;
            *(uint4*)&sB[r * LDB + c * 8] =
                *(const uint4*)(Bm + (size_t)r * UNITS + n0 + c * 8);
        }
    }
    __syncthreads();

    wmma::fragment<wmma::accumulator, 16, 16, 16, float> acc[2];
    wmma::fill_fragment(acc[0], 0.f);
    wmma::fill_fragment(acc[1], 0.f);

    const __nv_bfloat16* sA0 = sA + (wm * 32) * lda;
    const __nv_bfloat16* sA1 = sA + (wm * 32 + 16) * lda;
    const __nv_bfloat16* sBw = sB + wn * 16;

    #pragma unroll 8
    for (int k0 = 0; k0 < K; k0 += 16) {
        wmma::fragment<wmma::matrix_a, 16, 16, 16, __nv_bfloat16, wmma::row_major> a0, a1;
        wmma::fragment<wmma::matrix_b, 16, 16, 16, __nv_bfloat16, wmma::row_major> b0;
        wmma::load_matrix_sync(a0, sA0 + k0, lda);
        wmma::load_matrix_sync(a1, sA1 + k0, lda);
        wmma::load_matrix_sync(b0, sBw + k0 * LDB, LDB);
        wmma::mma_sync(acc[0], a0, b0, acc[0]);
        wmma::mma_sync(acc[1], a1, b0, acc[1]);
    }
    __syncthreads();    // done reading sA; safe to alias sC

    wmma::store_matrix_sync(&sC[(wm * 32) * LDC + wn * 16],      acc[0], LDC, wmma::mem_row_major);
    wmma::store_matrix_sync(&sC[(wm * 32 + 16) * LDC + wn * 16], acc[1], LDC, wmma::mem_row_major);
    __syncthreads();

    // pack to bf16 g_Z: thread -> row erow, 16 cols at ecb
    const int erow = (wid & 3) * 32 + lane;
    const int ecb  = (wid >> 2) * 16;
    const float* s = &sC[erow * LDC + ecb];
    __nv_bfloat162 p[8];
    #pragma unroll
    for (int q = 0; q < 8; q++) p[q] = __floats2bfloat162_rn(s[2*q], s[2*q+1]);
    __nv_bfloat16* dst = g_Z + (size_t)(m0 + erow) * UNITS + n0 + ecb;
    *(uint4*)dst       = *(uint4*)&p[0];
    *(uint4*)(dst + 8) = *(uint4*)&p[4];
}

// ---------------- persistent scan (HMMA, U resident, sync-free mainloop) ----------------
__device__ __forceinline__ void grid_sync(unsigned int target) {
    __syncthreads();
    if (threadIdx.x == 0) {
        __threadfence();
        atomicAdd(&g_arrive, 1u);
        volatile unsigned int* p = &g_arrive;
        while (*p < target) { }
        __threadfence();
    }
    __syncthreads();
}

__global__ __launch_bounds__(THREADS, 1) void scan_layer(int layer,
                                                         const float* __restrict__ bias,
                                                         unsigned int barBase) {
    extern __shared__ __align__(16) unsigned char smraw[];
    __nv_bfloat16* sA = (__nv_bfloat16*)(smraw + SM_A);
    __nv_bfloat16* sB = (__nv_bfloat16*)(smraw + SM_B);
    float*         sC = (float*)(smraw + SM_A);
    float*         sBias = (float*)(smraw + SM_BIAS);

    const int tid = threadIdx.x;
    const int wid = tid >> 5, lane = tid & 31;
    const int bid = blockIdx.x;
    const int n0 = (bid & 7) * BN;
    const int m0 = (bid >> 3) * BM;
    const int wm = wid & 3, wn = wid >> 2;

    // stage U[:, n0:n0+64] once per layer
    {
        const __nv_bfloat16* U = g_U[layer];
        for (int i = tid; i < UNITS * 8; i += THREADS) {
            int r = i >> 3, c = i & 7;
            *(uint4*)&sB[r * LDB + c * 8] =
                *(const uint4*)(U + (size_t)r * UNITS + n0 + c * 8);
        }
        if (tid < BN) sBias[tid] = bias[n0 + tid];
    }
    __syncthreads();

    // epilogue mapping: row erow, 16 cols at ecb
    const int erow = (wid & 3) * 32 + lane;
    const int ecb  = (wid >> 2) * 16;
    const size_t b_global = (size_t)(m0 + erow);
    const size_t aStride = (size_t)SEQ * UNITS;

    unsigned int tgt = barBase;

    for (int t = 0; t < SEQ; t++) {
        size_t eidx = (b_global * SEQ + t) * UNITS + n0 + ecb;
        if (t == 0) {
            const __nv_bfloat162* z2 = (const __nv_bfloat162*)(g_Z + eidx);
            __nv_bfloat162 o[8];
            #pragma unroll
            for (int c = 0; c < 8; c++) {
                __nv_bfloat162 z = z2[c];
                o[c] = __floats2bfloat162_rn(tanhf(__low2float(z)  + sBias[ecb + 2*c]),
                                             tanhf(__high2float(z) + sBias[ecb + 2*c + 1]));
            }
            __nv_bfloat16* dst = g_H + eidx;
            *(uint4*)dst       = *(uint4*)&o[0];
            *(uint4*)(dst + 8) = *(uint4*)&o[4];
        } else {
            // stage A = h_{t-1} tile (128 x 512)
            const __nv_bfloat16* A = g_H + (size_t)(t - 1) * UNITS;
            for (int i = tid; i < BM * 64; i += THREADS) {
                int r = i >> 6, c = i & 63;
                *(uint4*)&sA[r * LDA + c * 8] =
                    *(const uint4*)(A + (size_t)(m0 + r) * aStride + c * 8);
            }
            __syncthreads();

            wmma::fragment<wmma::accumulator, 16, 16, 16, float> acc[2];
            wmma::fill_fragment(acc[0], 0.f);
            wmma::fill_fragment(acc[1], 0.f);

            const __nv_bfloat16* sA0 = sA + (wm * 32) * LDA;
            const __nv_bfloat16* sA1 = sA + (wm * 32 + 16) * LDA;
            const __nv_bfloat16* sBw = sB + wn * 16;

            #pragma unroll 8
            for (int k0 = 0; k0 < UNITS; k0 += 16) {
                wmma::fragment<wmma::matrix_a, 16, 16, 16, __nv_bfloat16, wmma::row_major> a0, a1;
                wmma::fragment<wmma::matrix_b, 16, 16, 16, __nv_bfloat16, wmma::row_major> b0;
                wmma::load_matrix_sync(a0, sA0 + k0, LDA);
                wmma::load_matrix_sync(a1, sA1 + k0, LDA);
                wmma::load_matrix_sync(b0, sBw + k0 * LDB, LDB);
                wmma::mma_sync(acc[0], a0, b0, acc[0]);
                wmma::mma_sync(acc[1], a1, b0, acc[1]);
            }

            // prefetch Z while accumulators drain
            uint4 zr0, zr1;
            {
                const uint4* zp = (const uint4*)(g_Z + eidx);
                zr0 = zp[0]; zr1 = zp[1];
            }
            __syncthreads();    // done reading sA; alias sC

            wmma::store_matrix_sync(&sC[(wm * 32) * LDC + wn * 16],      acc[0], LDC, wmma::mem_row_major);
            wmma::store_matrix_sync(&sC[(wm * 32 + 16) * LDC + wn * 16], acc[1], LDC, wmma::mem_row_major);
            __syncthreads();

            const float* s = &sC[erow * LDC + ecb];
            const __nv_bfloat162* z2 = (const __nv_bfloat162*)&zr0;   // zr0/zr1 contiguous? safer below
            __nv_bfloat162 zbuf[8];
            *(uint4*)&zbuf[0] = zr0;
            *(uint4*)&zbuf[4] = zr1;
            __nv_bfloat162 o[8];
            #pragma unroll
            for (int c = 0; c < 8; c++) {
                float v0 = tanhf(s[2*c]     + __low2float(zbuf[c])  + sBias[ecb + 2*c]);
                float v1 = tanhf(s[2*c + 1] + __high2float(zbuf[c]) + sBias[ecb + 2*c + 1]);
                o[c] = __floats2bfloat162_rn(v0, v1);
            }
            __nv_bfloat16* dst = g_H + eidx;
            *(uint4*)dst       = *(uint4*)&o[0];
            *(uint4*)(dst + 8) = *(uint4*)&o[4];
            (void)z2;
        }

        if (t + 1 < SEQ) {
            tgt += NBLK;
            grid_sync(tgt);
        }
    }
}

// ---------------- head ----------------
__global__ void head(const float* __restrict__ Wo, const float* __restrict__ bo,
                     float* __restrict__ out) {
    int gt = blockIdx.x * blockDim.x + threadIdx.x;
    int w = gt >> 5, lane = gt & 31;
    if (w >= BATCH) return;
    const __nv_bfloat16* h = g_H + ((size_t)w * SEQ + (SEQ - 1)) * UNITS;
    float s = 0.f;
    for (int k = lane; k < UNITS; k += 32)
        s += __bfloat162float(h[k]) * Wo[k];
    #pragma unroll
    for (int o = 16; o; o >>= 1) s += __shfl_xor_sync(0xffffffffu, s, o);
    if (lane == 0) out[w] = 1.f / (1.f + expf(-(s + bo[0])));
}

// ---------------- launch ----------------
extern "C" void kernel_launch(void* const* d_in, const int* in_sizes, int n_in,
                              void* d_out, int out_size) {
    const int*   tokens = (const int*)d_in[0];
    const float* emb    = (const float*)d_in[1];
    const float* Wm[4]  = {(const float*)d_in[2],  (const float*)d_in[5],
                           (const float*)d_in[8],  (const float*)d_in[11]};
    const float* Um[4]  = {(const float*)d_in[3],  (const float*)d_in[6],
                           (const float*)d_in[9],  (const float*)d_in[12]};
    const float* bm[4]  = {(const float*)d_in[4],  (const float*)d_in[7],
                           (const float*)d_in[10], (const float*)d_in[13]};
    const float* Wo = (const float*)d_in[14];
    const float* bo = (const float*)d_in[15];
    float* out = (float*)d_out;

    cudaFuncSetAttribute(gemm_in,    cudaFuncAttributeMaxDynamicSharedMemorySize, SM_TOTAL);
    cudaFuncSetAttribute(scan_layer, cudaFuncAttributeMaxDynamicSharedMemorySize, SM_TOTAL);

    void* barAddr = nullptr;
    cudaGetSymbolAddress(&barAddr, g_arrive);
    cudaMemsetAsync(barAddr, 0, sizeof(unsigned int));

    embed_kernel<<<(int)(((size_t)BT * EMBP + 255) / 256), 256>>>(tokens, emb);
    prep_w1<<<(EMBP * UNITS + 255) / 256, 256>>>(Wm[0]);
    for (int l = 1; l < 4; l++)
        prep_w<<<(UNITS * UNITS + 255) / 256, 256>>>(Wm[l], l - 1);
    for (int l = 0; l < 4; l++)
        prep_u<<<(UNITS * UNITS + 255) / 256, 256>>>(Um[l], l);

    dim3 gin(UNITS / BN, BT / BM);     // (8, 1280)
    for (int l = 0; l < 4; l++) {
        gemm_in<<<gin, THREADS, SM_TOTAL>>>(l);
        scan_layer<<<NBLK, THREADS, SM_TOTAL>>>(l, bm[l], (unsigned)(l * (SEQ - 1) * NBLK));
    }
    head<<<(BATCH * 32 + 255) / 256, 256>>>(Wo, bo, out);
}

// round 6
// speedup vs baseline: 2.3757x; 1.1602x over previous
#include <cuda_runtime.h>
#include <cuda_bf16.h>
#include <mma.h>
#include <math.h>
#include <cstdint>

using namespace nvcuda;

#define BATCH 2048
#define SEQ   80
#define UNITS 512
#define EMB   100
#define EMBP  128
#define BT    (BATCH*SEQ)
#define THREADS 512

// ---- scan tiling ----
#define BM 128
#define BN 64
#define NBLK 128                    // 16 m-groups x 8 n-tiles
#define LDSA 136                    // scan A-chunk stride (128+8)
#define LDSU 72                     // U stride (64+8)
#define LDSC 68
#define SCAN_ABUF 34816             // 128*136*2
#define SM_U    0                   // 512*72*2 = 73728
#define SM_A    73728               // 3 * 34816 = 104448 (sC aliases buf0)
#define SM_BIAS 178176
#define SCAN_SMEM 178432

// ---- bulk tiling ----
#define GBN 128
#define LDBB 136                    // bulk B stride (128+8)
#define LDBA 72                     // bulk A-chunk stride (64+8)
#define LDBC 132
#define BULK_ABUF 18432             // 128*72*2
#define GM_B 0                      // 512*136*2 = 139264 (sC aliases here)
#define GM_A 139264                 // 3 * 18432 = 55296
#define BULK_SMEM 194560

// ---------------- persistent device scratch ----------------
__device__ __nv_bfloat16 g_X[(size_t)BT * EMBP];
__device__ __nv_bfloat16 g_Z[(size_t)BT * UNITS];
__device__ __nv_bfloat16 g_H[(size_t)BT * UNITS];
__device__ __nv_bfloat16 g_W1p[EMBP * UNITS];
__device__ __nv_bfloat16 g_W[3][UNITS * UNITS];
__device__ __nv_bfloat16 g_U[4][UNITS * UNITS];
__device__ unsigned int  g_arr[16];                 // per-m-group barrier counters

// ---------------- cp.async helpers ----------------
__device__ __forceinline__ uint32_t smem_u32(const void* p) {
    uint32_t a;
    asm("{ .reg .u64 t; cvta.to.shared.u64 t, %1; cvt.u32.u64 %0, t; }" : "=r"(a) : "l"(p));
    return a;
}
__device__ __forceinline__ void cp16(uint32_t dst, const void* src) {
    asm volatile("cp.async.cg.shared.global [%0], [%1], 16;" :: "r"(dst), "l"(src));
}
#define CP_COMMIT() asm volatile("cp.async.commit_group;" ::: "memory")
#define CP_WAIT1()  asm volatile("cp.async.wait_group 1;" ::: "memory")
#define CP_WAIT0()  asm volatile("cp.async.wait_group 0;" ::: "memory")

// ---------------- prep kernels ----------------
__global__ void embed_kernel(const int* __restrict__ tokens, const float* __restrict__ emb) {
    size_t idx = (size_t)blockIdx.x * blockDim.x + threadIdx.x;
    if (idx >= (size_t)BT * EMBP) return;
    size_t row = idx >> 7;
    int col = (int)(idx & 127);
    int tok = tokens[row];
    float v = (col < EMB) ? emb[(size_t)tok * EMB + col] : 0.f;
    g_X[idx] = __float2bfloat16(v);
}

__global__ void prep_w1(const float* __restrict__ W1) {
    int idx = blockIdx.x * blockDim.x + threadIdx.x;
    if (idx >= EMBP * UNITS) return;
    int k = idx >> 9, n = idx & 511;
    g_W1p[idx] = __float2bfloat16(k < EMB ? W1[k * UNITS + n] : 0.f);
}

__global__ void prep_w(const float* __restrict__ src, int l) {
    int idx = blockIdx.x * blockDim.x + threadIdx.x;
    if (idx >= UNITS * UNITS) return;
    g_W[l][idx] = __float2bfloat16(src[idx]);
}

__global__ void prep_u(const float* __restrict__ src, int l) {
    int idx = blockIdx.x * blockDim.x + threadIdx.x;
    if (idx >= UNITS * UNITS) return;
    g_U[l][idx] = __float2bfloat16(src[idx]);
}

// ---------------- bulk input GEMM: g_Z = A @ W, 128x128 tiles, cp.async pipeline ----------------
__global__ __launch_bounds__(THREADS, 1) void gemm_in(int layer) {
    extern __shared__ __align__(16) unsigned char smraw[];
    __nv_bfloat16* sB = (__nv_bfloat16*)(smraw + GM_B);
    float*         sC = (float*)(smraw + GM_B);        // alias after last MMA

    const __nv_bfloat16* Ag;
    const __nv_bfloat16* Bg;
    int K, aStride;
    if (layer == 0) { Ag = g_X; K = EMBP;  Bg = g_W1p;        aStride = EMBP; }
    else            { Ag = g_H; K = UNITS; Bg = g_W[layer-1]; aStride = UNITS; }
    const int KC = K / 64;

    const int n0 = blockIdx.x * GBN;
    const int m0 = blockIdx.y * BM;
    const int tid = threadIdx.x;
    const int wid = tid >> 5;
    const int wm = wid & 3, wn = wid >> 2;

    const uint32_t sbase = smem_u32(smraw);
    const uint32_t aBase = sbase + GM_A;

    // stage B [K x 128] via cp.async
    for (int i = tid; i < K * 16; i += THREADS) {
        int r = i >> 4, c = i & 15;
        cp16(sbase + GM_B + r * (LDBB * 2) + c * 16,
             Bg + (size_t)r * UNITS + n0 + c * 8);
    }
    // prologue: A chunk 0
    {
        #pragma unroll
        for (int j = 0; j < 2; j++) {
            int i = tid + j * THREADS;
            int r = i >> 3, c = i & 7;
            cp16(aBase + r * (LDBA * 2) + c * 16,
                 Ag + (size_t)(m0 + r) * aStride + c * 8);
        }
    }
    CP_COMMIT();

    wmma::fragment<wmma::accumulator, 16, 16, 16, float> acc[2][2];
    #pragma unroll
    for (int i = 0; i < 2; i++)
        #pragma unroll
        for (int j = 0; j < 2; j++) wmma::fill_fragment(acc[i][j], 0.f);

    int buf = 0;
    for (int kc = 0; kc < KC; kc++) {
        if (kc + 1 < KC) {
            int nb = buf + 1; if (nb == 3) nb = 0;
            #pragma unroll
            for (int j = 0; j < 2; j++) {
                int i = tid + j * THREADS;
                int r = i >> 3, c = i & 7;
                cp16(aBase + nb * BULK_ABUF + r * (LDBA * 2) + c * 16,
                     Ag + (size_t)(m0 + r) * aStride + (kc + 1) * 64 + c * 8);
            }
            CP_COMMIT();
            CP_WAIT1();
        } else {
            CP_WAIT0();
        }
        __syncthreads();

        const __nv_bfloat16* sA = (const __nv_bfloat16*)(smraw + GM_A + buf * BULK_ABUF);
        #pragma unroll
        for (int kk = 0; kk < 64; kk += 16) {
            wmma::fragment<wmma::matrix_a, 16, 16, 16, __nv_bfloat16, wmma::row_major> a0, a1;
            wmma::fragment<wmma::matrix_b, 16, 16, 16, __nv_bfloat16, wmma::row_major> b0, b1;
            wmma::load_matrix_sync(a0, sA + (wm * 32) * LDBA + kk, LDBA);
            wmma::load_matrix_sync(a1, sA + (wm * 32 + 16) * LDBA + kk, LDBA);
            wmma::load_matrix_sync(b0, sB + (kc * 64 + kk) * LDBB + wn * 32, LDBB);
            wmma::load_matrix_sync(b1, sB + (kc * 64 + kk) * LDBB + wn * 32 + 16, LDBB);
            wmma::mma_sync(acc[0][0], a0, b0, acc[0][0]);
            wmma::mma_sync(acc[0][1], a0, b1, acc[0][1]);
            wmma::mma_sync(acc[1][0], a1, b0, acc[1][0]);
            wmma::mma_sync(acc[1][1], a1, b1, acc[1][1]);
        }
        buf++; if (buf == 3) buf = 0;
    }
    __syncthreads();       // done reading sB; alias sC

    #pragma unroll
    for (int i = 0; i < 2; i++)
        #pragma unroll
        for (int j = 0; j < 2; j++)
            wmma::store_matrix_sync(&sC[(wm * 32 + i * 16) * LDBC + wn * 32 + j * 16],
                                    acc[i][j], LDBC, wmma::mem_row_major);
    __syncthreads();

    // pack to bf16: thread -> row tid>>2, 32 cols at (tid&3)*32
    {
        const int erow = tid >> 2;
        const int ecb  = (tid & 3) * 32;
        const float* s = &sC[erow * LDBC + ecb];
        __nv_bfloat162 p[16];
        #pragma unroll
        for (int q = 0; q < 16; q++) p[q] = __floats2bfloat162_rn(s[2*q], s[2*q+1]);
        __nv_bfloat16* dst = g_Z + (size_t)(m0 + erow) * UNITS + n0 + ecb;
        #pragma unroll
        for (int q = 0; q < 4; q++)
            *(uint4*)(dst + q * 8) = *(uint4*)&p[q * 4];
    }
}

// ---------------- m-group barrier ----------------
__device__ __forceinline__ void group_sync(int mg, unsigned int target) {
    __syncthreads();
    if (threadIdx.x == 0) {
        __threadfence();
        atomicAdd(&g_arr[mg], 1u);
        volatile unsigned int* p = &g_arr[mg];
        while (*p < target) { }
        __threadfence();
    }
    __syncthreads();
}

// ---------------- persistent scan: cp.async pipelined HMMA, U resident ----------------
__global__ __launch_bounds__(THREADS, 1) void scan_layer(int layer,
                                                         const float* __restrict__ bias,
                                                         unsigned int barBase) {
    extern __shared__ __align__(16) unsigned char smraw[];
    __nv_bfloat16* sU = (__nv_bfloat16*)(smraw + SM_U);
    float*         sC = (float*)(smraw + SM_A);        // alias A buffers in epilogue
    float*         sBias = (float*)(smraw + SM_BIAS);

    const int tid = threadIdx.x;
    const int wid = tid >> 5, lane = tid & 31;
    const int bid = blockIdx.x;
    const int n0 = (bid & 7) * BN;
    const int mg = bid >> 3;
    const int m0 = mg * BM;
    const int wm = wid & 3, wn = wid >> 2;

    const uint32_t sbase = smem_u32(smraw);
    const uint32_t aBase = sbase + SM_A;

    // stage U[:, n0:n0+64] once per layer
    {
        const __nv_bfloat16* U = g_U[layer];
        for (int i = tid; i < UNITS * 8; i += THREADS) {
            int r = i >> 3, c = i & 7;
            *(uint4*)((__nv_bfloat16*)(smraw + SM_U) + r * LDSU + c * 8) =
                *(const uint4*)(U + (size_t)r * UNITS + n0 + c * 8);
        }
        if (tid < BN) sBias[tid] = bias[n0 + tid];
    }
    __syncthreads();

    const int erow = (wid & 3) * 32 + lane;
    const int ecb  = (wid >> 2) * 16;
    const size_t b_global = (size_t)(m0 + erow);
    const size_t aStride = (size_t)SEQ * UNITS;

    unsigned int tgt = barBase;

    for (int t = 0; t < SEQ; t++) {
        size_t eidx = (b_global * SEQ + t) * UNITS + n0 + ecb;
        if (t == 0) {
            const __nv_bfloat162* z2 = (const __nv_bfloat162*)(g_Z + eidx);
            __nv_bfloat162 o[8];
            #pragma unroll
            for (int c = 0; c < 8; c++) {
                __nv_bfloat162 z = z2[c];
                o[c] = __floats2bfloat162_rn(tanhf(__low2float(z)  + sBias[ecb + 2*c]),
                                             tanhf(__high2float(z) + sBias[ecb + 2*c + 1]));
            }
            __nv_bfloat16* dst = g_H + eidx;
            *(uint4*)dst       = *(uint4*)&o[0];
            *(uint4*)(dst + 8) = *(uint4*)&o[4];
        } else {
            const __nv_bfloat16* A = g_H + (size_t)(t - 1) * UNITS;

            // prologue: chunk 0
            {
                #pragma unroll
                for (int j = 0; j < 4; j++) {
                    int i = tid + j * THREADS;
                    int r = i >> 4, c = i & 15;
                    cp16(aBase + r * (LDSA * 2) + c * 16,
                         A + (size_t)(m0 + r) * aStride + c * 8);
                }
            }
            CP_COMMIT();

            // prefetch Z (hidden behind the chunk pipeline)
            uint4 zr0, zr1;
            {
                const uint4* zp = (const uint4*)(g_Z + eidx);
                zr0 = zp[0]; zr1 = zp[1];
            }

            wmma::fragment<wmma::accumulator, 16, 16, 16, float> acc[2];
            wmma::fill_fragment(acc[0], 0.f);
            wmma::fill_fragment(acc[1], 0.f);

            int buf = 0;
            #pragma unroll
            for (int kc = 0; kc < 4; kc++) {
                if (kc < 3) {
                    int nb = buf + 1; if (nb == 3) nb = 0;
                    #pragma unroll
                    for (int j = 0; j < 4; j++) {
                        int i = tid + j * THREADS;
                        int r = i >> 4, c = i & 15;
                        cp16(aBase + nb * SCAN_ABUF + r * (LDSA * 2) + c * 16,
                             A + (size_t)(m0 + r) * aStride + (kc + 1) * 128 + c * 8);
                    }
                    CP_COMMIT();
                    CP_WAIT1();
                } else {
                    CP_WAIT0();
                }
                __syncthreads();

                const __nv_bfloat16* sA = (const __nv_bfloat16*)(smraw + SM_A + buf * SCAN_ABUF);
                const __nv_bfloat16* sBw = sU + kc * 128 * LDSU + wn * 16;
                #pragma unroll
                for (int kk = 0; kk < 128; kk += 16) {
                    wmma::fragment<wmma::matrix_a, 16, 16, 16, __nv_bfloat16, wmma::row_major> a0, a1;
                    wmma::fragment<wmma::matrix_b, 16, 16, 16, __nv_bfloat16, wmma::row_major> b0;
                    wmma::load_matrix_sync(a0, sA + (wm * 32) * LDSA + kk, LDSA);
                    wmma::load_matrix_sync(a1, sA + (wm * 32 + 16) * LDSA + kk, LDSA);
                    wmma::load_matrix_sync(b0, sBw + kk * LDSU, LDSU);
                    wmma::mma_sync(acc[0], a0, b0, acc[0]);
                    wmma::mma_sync(acc[1], a1, b0, acc[1]);
                }
                buf++; if (buf == 3) buf = 0;
            }
            __syncthreads();   // done reading A buffers; alias sC

            wmma::store_matrix_sync(&sC[(wm * 32) * LDSC + wn * 16],      acc[0], LDSC, wmma::mem_row_major);
            wmma::store_matrix_sync(&sC[(wm * 32 + 16) * LDSC + wn * 16], acc[1], LDSC, wmma::mem_row_major);
            __syncthreads();

            const float* s = &sC[erow * LDSC + ecb];
            __nv_bfloat162 zbuf[8];
            *(uint4*)&zbuf[0] = zr0;
            *(uint4*)&zbuf[4] = zr1;
            __nv_bfloat162 o[8];
            #pragma unroll
            for (int c = 0; c < 8; c++) {
                float v0 = tanhf(s[2*c]     + __low2float(zbuf[c])  + sBias[ecb + 2*c]);
                float v1 = tanhf(s[2*c + 1] + __high2float(zbuf[c]) + sBias[ecb + 2*c + 1]);
                o[c] = __floats2bfloat162_rn(v0, v1);
            }
            __nv_bfloat16* dst = g_H + eidx;
            *(uint4*)dst       = *(uint4*)&o[0];
            *(uint4*)(dst + 8) = *(uint4*)&o[4];
        }

        if (t + 1 < SEQ) {
            tgt += 8;                 // 8 n-tile blocks per m-group
            group_sync(mg, tgt);
        }
    }
}

// ---------------- head ----------------
__global__ void head(const float* __restrict__ Wo, const float* __restrict__ bo,
                     float* __restrict__ out) {
    int gt = blockIdx.x * blockDim.x + threadIdx.x;
    int w = gt >> 5, lane = gt & 31;
    if (w >= BATCH) return;
    const __nv_bfloat16* h = g_H + ((size_t)w * SEQ + (SEQ - 1)) * UNITS;
    float s = 0.f;
    for (int k = lane; k < UNITS; k += 32)
        s += __bfloat162float(h[k]) * Wo[k];
    #pragma unroll
    for (int o = 16; o; o >>= 1) s += __shfl_xor_sync(0xffffffffu, s, o);
    if (lane == 0) out[w] = 1.f / (1.f + expf(-(s + bo[0])));
}

// ---------------- launch ----------------
extern "C" void kernel_launch(void* const* d_in, const int* in_sizes, int n_in,
                              void* d_out, int out_size) {
    const int*   tokens = (const int*)d_in[0];
    const float* emb    = (const float*)d_in[1];
    const float* Wm[4]  = {(const float*)d_in[2],  (const float*)d_in[5],
                           (const float*)d_in[8],  (const float*)d_in[11]};
    const float* Um[4]  = {(const float*)d_in[3],  (const float*)d_in[6],
                           (const float*)d_in[9],  (const float*)d_in[12]};
    const float* bm[4]  = {(const float*)d_in[4],  (const float*)d_in[7],
                           (const float*)d_in[10], (const float*)d_in[13]};
    const float* Wo = (const float*)d_in[14];
    const float* bo = (const float*)d_in[15];
    float* out = (float*)d_out;

    cudaFuncSetAttribute(gemm_in,    cudaFuncAttributeMaxDynamicSharedMemorySize, BULK_SMEM);
    cudaFuncSetAttribute(scan_layer, cudaFuncAttributeMaxDynamicSharedMemorySize, SCAN_SMEM);

    void* barAddr = nullptr;
    cudaGetSymbolAddress(&barAddr, g_arr);
    cudaMemsetAsync(barAddr, 0, 16 * sizeof(unsigned int));

    embed_kernel<<<(int)(((size_t)BT * EMBP + 255) / 256), 256>>>(tokens, emb);
    prep_w1<<<(EMBP * UNITS + 255) / 256, 256>>>(Wm[0]);
    for (int l = 1; l < 4; l++)
        prep_w<<<(UNITS * UNITS + 255) / 256, 256>>>(Wm[l], l - 1);
    for (int l = 0; l < 4; l++)
        prep_u<<<(UNITS * UNITS + 255) / 256, 256>>>(Um[l], l);

    dim3 gin(UNITS / GBN, BT / BM);     // (4, 1280)
    for (int l = 0; l < 4; l++) {
        gemm_in<<<gin, THREADS, BULK_SMEM>>>(l);
        scan_layer<<<NBLK, THREADS, SCAN_SMEM>>>(l, bm[l], (unsigned)(l * (SEQ - 1) * 8));
    }
    head<<<(BATCH * 32 + 255) / 256, 256>>>(Wo, bo, out);
}

// round 7
// speedup vs baseline: 2.5378x; 1.0683x over previous
#include <cuda_runtime.h>
#include <cuda_bf16.h>
#include <mma.h>
#include <math.h>
#include <cstdint>

using namespace nvcuda;

#define BATCH 2048
#define SEQ   80
#define UNITS 512
#define EMB   100
#define EMBP  128
#define BT    (BATCH*SEQ)
#define THREADS 512

// ---- scan tiling ----
#define BM 128
#define BN 64
#define NBLK 128                 // 16 m-groups x 8 n-tiles
#define LDSU 72                  // U/W smem stride (64+8)
#define LDSA 72                  // A chunk stride (64+8)
#define LDSC 68
#define ABUF 18432               // 128*72*2
#define SM_U    0                // 512*72*2 = 73728
#define SM_W    73728            // 512*72*2 = 73728
#define SM_A    147456           // 3*18432 = 55296 (sC f32 aliases buf0/1)
#define SM_BIAS 202752
#define SCAN_SMEM 203008

// ---- layer-0 bulk tiling (from round 6) ----
#define GBN 128
#define LDBB 136
#define LDBA 72
#define LDBC 132
#define BULK_ABUF 18432
#define GM_B 0
#define GM_A 139264
#define BULK_SMEM 194560

// ---------------- persistent device scratch ----------------
__device__ __nv_bfloat16 g_X[(size_t)BT * EMBP];
__device__ __nv_bfloat16 g_Z[(size_t)BT * UNITS];
__device__ __nv_bfloat16 g_H[(size_t)BT * UNITS];
__device__ __nv_bfloat16 g_W1p[EMBP * UNITS];
__device__ __nv_bfloat16 g_W[3][UNITS * UNITS];   // g_W[l] = Wm[l+1]
__device__ __nv_bfloat16 g_U[4][UNITS * UNITS];
__device__ unsigned int  g_arr[16];

// ---------------- helpers ----------------
__device__ __forceinline__ uint32_t smem_u32(const void* p) {
    uint32_t a;
    asm("{ .reg .u64 t; cvta.to.shared.u64 t, %1; cvt.u32.u64 %0, t; }" : "=r"(a) : "l"(p));
    return a;
}
__device__ __forceinline__ void cp16(uint32_t dst, const void* src) {
    asm volatile("cp.async.cg.shared.global [%0], [%1], 16;" :: "r"(dst), "l"(src));
}
#define CP_COMMIT() asm volatile("cp.async.commit_group;" ::: "memory")
#define CP_WAIT1()  asm volatile("cp.async.wait_group 1;" ::: "memory")
#define CP_WAIT0()  asm volatile("cp.async.wait_group 0;" ::: "memory")

__device__ __forceinline__ float tanhfast(float x) {
    float y;
    asm("tanh.approx.f32 %0, %1;" : "=f"(y) : "f"(x));
    return y;
}

// ---------------- embed + fused weight prep ----------------
__global__ void embed_kernel(const int* __restrict__ tokens, const float* __restrict__ emb) {
    size_t idx = (size_t)blockIdx.x * blockDim.x + threadIdx.x;
    if (idx >= (size_t)BT * EMBP) return;
    size_t row = idx >> 7;
    int col = (int)(idx & 127);
    int tok = tokens[row];
    float v = (col < EMB) ? emb[(size_t)tok * EMB + col] : 0.f;
    g_X[idx] = __float2bfloat16(v);
}

__global__ void prep_all(const float* __restrict__ W1, const float* __restrict__ W2,
                         const float* __restrict__ W3, const float* __restrict__ W4,
                         const float* __restrict__ U1, const float* __restrict__ U2,
                         const float* __restrict__ U3, const float* __restrict__ U4) {
    int y = blockIdx.y;
    int idx = blockIdx.x * blockDim.x + threadIdx.x;
    if (y == 0) {
        if (idx < EMBP * UNITS) {
            int k = idx >> 9, n = idx & 511;
            g_W1p[idx] = __float2bfloat16(k < EMB ? W1[k * UNITS + n] : 0.f);
        }
    } else if (y <= 3) {
        const float* s = (y == 1) ? W2 : (y == 2) ? W3 : W4;
        if (idx < UNITS * UNITS) g_W[y - 1][idx] = __float2bfloat16(s[idx]);
    } else {
        const float* s = (y == 4) ? U1 : (y == 5) ? U2 : (y == 6) ? U3 : U4;
        if (idx < UNITS * UNITS) g_U[y - 4][idx] = __float2bfloat16(s[idx]);
    }
}

// ---------------- layer-0 bulk GEMM: g_Z = X @ W1p (K=128) ----------------
__global__ __launch_bounds__(THREADS, 1) void gemm0() {
    extern __shared__ __align__(16) unsigned char smraw[];
    __nv_bfloat16* sB = (__nv_bfloat16*)(smraw + GM_B);
    float*         sC = (float*)(smraw + GM_B);

    const __nv_bfloat16* Ag = g_X;
    const __nv_bfloat16* Bg = g_W1p;
    const int K = EMBP, aStride = EMBP, KC = 2;

    const int n0 = blockIdx.x * GBN;
    const int m0 = blockIdx.y * BM;
    const int tid = threadIdx.x;
    const int wid = tid >> 5;
    const int wm = wid & 3, wn = wid >> 2;

    const uint32_t sbase = smem_u32(smraw);
    const uint32_t aBase = sbase + GM_A;

    for (int i = tid; i < K * 16; i += THREADS) {
        int r = i >> 4, c = i & 15;
        cp16(sbase + GM_B + r * (LDBB * 2) + c * 16, Bg + (size_t)r * UNITS + n0 + c * 8);
    }
    {
        #pragma unroll
        for (int j = 0; j < 2; j++) {
            int i = tid + j * THREADS;
            int r = i >> 3, c = i & 7;
            cp16(aBase + r * (LDBA * 2) + c * 16, Ag + (size_t)(m0 + r) * aStride + c * 8);
        }
    }
    CP_COMMIT();

    wmma::fragment<wmma::accumulator, 16, 16, 16, float> acc[2][2];
    #pragma unroll
    for (int i = 0; i < 2; i++)
        #pragma unroll
        for (int j = 0; j < 2; j++) wmma::fill_fragment(acc[i][j], 0.f);

    int buf = 0;
    for (int kc = 0; kc < KC; kc++) {
        if (kc + 1 < KC) {
            int nb = buf + 1;
            #pragma unroll
            for (int j = 0; j < 2; j++) {
                int i = tid + j * THREADS;
                int r = i >> 3, c = i & 7;
                cp16(aBase + nb * BULK_ABUF + r * (LDBA * 2) + c * 16,
                     Ag + (size_t)(m0 + r) * aStride + (kc + 1) * 64 + c * 8);
            }
            CP_COMMIT();
            CP_WAIT1();
        } else {
            CP_WAIT0();
        }
        __syncthreads();

        const __nv_bfloat16* sA = (const __nv_bfloat16*)(smraw + GM_A + buf * BULK_ABUF);
        #pragma unroll
        for (int kk = 0; kk < 64; kk += 16) {
            wmma::fragment<wmma::matrix_a, 16, 16, 16, __nv_bfloat16, wmma::row_major> a0, a1;
            wmma::fragment<wmma::matrix_b, 16, 16, 16, __nv_bfloat16, wmma::row_major> b0, b1;
            wmma::load_matrix_sync(a0, sA + (wm * 32) * LDBA + kk, LDBA);
            wmma::load_matrix_sync(a1, sA + (wm * 32 + 16) * LDBA + kk, LDBA);
            wmma::load_matrix_sync(b0, sB + (kc * 64 + kk) * LDBB + wn * 32, LDBB);
            wmma::load_matrix_sync(b1, sB + (kc * 64 + kk) * LDBB + wn * 32 + 16, LDBB);
            wmma::mma_sync(acc[0][0], a0, b0, acc[0][0]);
            wmma::mma_sync(acc[0][1], a0, b1, acc[0][1]);
            wmma::mma_sync(acc[1][0], a1, b0, acc[1][0]);
            wmma::mma_sync(acc[1][1], a1, b1, acc[1][1]);
        }
        buf++;
    }
    __syncthreads();

    #pragma unroll
    for (int i = 0; i < 2; i++)
        #pragma unroll
        for (int j = 0; j < 2; j++)
            wmma::store_matrix_sync(&sC[(wm * 32 + i * 16) * LDBC + wn * 32 + j * 16],
                                    acc[i][j], LDBC, wmma::mem_row_major);
    __syncthreads();

    {
        const int erow = tid >> 2;
        const int ecb  = (tid & 3) * 32;
        const float* s = &sC[erow * LDBC + ecb];
        __nv_bfloat162 p[16];
        #pragma unroll
        for (int q = 0; q < 16; q++) p[q] = __floats2bfloat162_rn(s[2*q], s[2*q+1]);
        __nv_bfloat16* dst = g_Z + (size_t)(m0 + erow) * UNITS + n0 + ecb;
        #pragma unroll
        for (int q = 0; q < 4; q++)
            *(uint4*)(dst + q * 8) = *(uint4*)&p[q * 4];
    }
}

// ---------------- fused persistent scan: recurrence + next-layer input GEMM ----------------
__global__ __launch_bounds__(THREADS, 1) void scan_layer(int layer, const float* __restrict__ bias,
                                                         int hasZ, unsigned barBase) {
    extern __shared__ __align__(16) unsigned char smraw[];
    __nv_bfloat16* sU = (__nv_bfloat16*)(smraw + SM_U);
    __nv_bfloat16* sW = (__nv_bfloat16*)(smraw + SM_W);
    float*         sC = (float*)(smraw + SM_A);
    float*         sBias = (float*)(smraw + SM_BIAS);
    const uint32_t aBase = smem_u32(smraw) + SM_A;

    const int tid = threadIdx.x;
    const int wid = tid >> 5, lane = tid & 31;
    const int bid = blockIdx.x;
    const int n0 = (bid & 7) * BN;
    const int mg = bid >> 3;
    const int m0 = mg * BM;
    const int wm = wid & 3, wn = wid >> 2;

    // stage U[:, n0:n0+64] and (if hasZ) Wnext[:, n0:n0+64], once per layer
    {
        const __nv_bfloat16* U = g_U[layer];
        #pragma unroll
        for (int j = 0; j < 8; j++) {
            int i = tid + j * THREADS;
            int r = i >> 3, c = i & 7;
            *(uint4*)&sU[r * LDSU + c * 8] = *(const uint4*)(U + (size_t)r * UNITS + n0 + c * 8);
        }
        if (hasZ) {
            const __nv_bfloat16* W = g_W[layer];
            #pragma unroll
            for (int j = 0; j < 8; j++) {
                int i = tid + j * THREADS;
                int r = i >> 3, c = i & 7;
                *(uint4*)&sW[r * LDSU + c * 8] = *(const uint4*)(W + (size_t)r * UNITS + n0 + c * 8);
            }
        }
        if (tid < BN) sBias[tid] = bias[n0 + tid];
    }
    __syncthreads();

    const int erow = (wid & 3) * 32 + lane;
    const int ecb  = (wid >> 2) * 16;
    const size_t aStride = (size_t)SEQ * UNITS;
    const size_t rowbase = (size_t)(m0 + erow) * SEQ;

    unsigned tgt = barBase;
    const int itMax = hasZ ? SEQ : (SEQ - 1);

    for (int it = 0; it <= itMax; it++) {
        const bool doRec = (it < SEQ);
        const bool doZ   = (hasZ && it >= 1);

        if (it == 0) {
            // h_0 = tanh(Z_0 + b)
            size_t eidx = rowbase * UNITS + n0 + ecb;
            uint4 z0 = *(const uint4*)(g_Z + eidx);
            uint4 z1 = *(const uint4*)(g_Z + eidx + 8);
            __nv_bfloat162 zb[8];
            *(uint4*)&zb[0] = z0; *(uint4*)&zb[4] = z1;
            __nv_bfloat162 o[8];
            #pragma unroll
            for (int c = 0; c < 8; c++)
                o[c] = __floats2bfloat162_rn(tanhfast(__low2float(zb[c])  + sBias[ecb + 2*c]),
                                             tanhfast(__high2float(zb[c]) + sBias[ecb + 2*c + 1]));
            __nv_bfloat16* dst = g_H + eidx;
            *(uint4*)dst       = *(uint4*)&o[0];
            *(uint4*)(dst + 8) = *(uint4*)&o[4];

            tgt += 8;
            __syncthreads();
            if (tid == 0) {
                __threadfence();
                atomicAdd(&g_arr[mg], 1u);
                volatile unsigned int* p = &g_arr[mg];
                while (*p < tgt) { }
                __threadfence();
            }
            __syncthreads();
            continue;
        }

        const __nv_bfloat16* A = g_H + (size_t)(it - 1) * UNITS;

        // prologue: A chunks 0,1 (depth-2 pipeline start)
        #pragma unroll
        for (int cidx = 0; cidx < 2; cidx++) {
            #pragma unroll
            for (int j = 0; j < 2; j++) {
                int i = tid + j * THREADS;
                int r = i >> 3, c = i & 7;
                cp16(aBase + cidx * ABUF + r * (LDSA * 2) + c * 16,
                     A + (size_t)(m0 + r) * aStride + cidx * 64 + c * 8);
            }
            CP_COMMIT();
        }

        // own-Z prefetch for the h epilogue
        uint4 zr0, zr1;
        if (doRec) {
            const uint4* zp = (const uint4*)(g_Z + (rowbase + it) * UNITS + n0 + ecb);
            zr0 = zp[0]; zr1 = zp[1];
        }

        wmma::fragment<wmma::accumulator, 16, 16, 16, float> accR[2], accZ[2];
        if (doRec) { wmma::fill_fragment(accR[0], 0.f); wmma::fill_fragment(accR[1], 0.f); }
        if (doZ)   { wmma::fill_fragment(accZ[0], 0.f); wmma::fill_fragment(accZ[1], 0.f); }

        // 8 chunks of 64 k-cols, 3 buffers, 1 sync per chunk
        for (int kc = 0; kc < 8; kc++) {
            if (kc < 7) CP_WAIT1(); else CP_WAIT0();
            __syncthreads();
            if (kc + 2 < 8) {
                int nb = (kc + 2) % 3;
                #pragma unroll
                for (int j = 0; j < 2; j++) {
                    int i = tid + j * THREADS;
                    int r = i >> 3, c = i & 7;
                    cp16(aBase + nb * ABUF + r * (LDSA * 2) + c * 16,
                         A + (size_t)(m0 + r) * aStride + (kc + 2) * 64 + c * 8);
                }
                CP_COMMIT();
            }
            const __nv_bfloat16* sA  = (const __nv_bfloat16*)(smraw + SM_A + (kc % 3) * ABUF);
            const __nv_bfloat16* sUw = sU + (kc * 64) * LDSU + wn * 16;
            const __nv_bfloat16* sWw = sW + (kc * 64) * LDSU + wn * 16;
            #pragma unroll
            for (int kk = 0; kk < 64; kk += 16) {
                wmma::fragment<wmma::matrix_a, 16, 16, 16, __nv_bfloat16, wmma::row_major> a0, a1;
                wmma::load_matrix_sync(a0, sA + (wm * 32) * LDSA + kk, LDSA);
                wmma::load_matrix_sync(a1, sA + (wm * 32 + 16) * LDSA + kk, LDSA);
                if (doRec) {
                    wmma::fragment<wmma::matrix_b, 16, 16, 16, __nv_bfloat16, wmma::row_major> bU;
                    wmma::load_matrix_sync(bU, sUw + kk * LDSU, LDSU);
                    wmma::mma_sync(accR[0], a0, bU, accR[0]);
                    wmma::mma_sync(accR[1], a1, bU, accR[1]);
                }
                if (doZ) {
                    wmma::fragment<wmma::matrix_b, 16, 16, 16, __nv_bfloat16, wmma::row_major> bW;
                    wmma::load_matrix_sync(bW, sWw + kk * LDSU, LDSU);
                    wmma::mma_sync(accZ[0], a0, bW, accZ[0]);
                    wmma::mma_sync(accZ[1], a1, bW, accZ[1]);
                }
            }
        }
        __syncthreads();   // all MMA done; A buffers (and sC alias) free

        if (doRec) {
            // h_t = tanh(R + Z + b)
            wmma::store_matrix_sync(&sC[(wm * 32) * LDSC + wn * 16],      accR[0], LDSC, wmma::mem_row_major);
            wmma::store_matrix_sync(&sC[(wm * 32 + 16) * LDSC + wn * 16], accR[1], LDSC, wmma::mem_row_major);
            __syncthreads();
            const float* s = &sC[erow * LDSC + ecb];
            __nv_bfloat162 zb[8];
            *(uint4*)&zb[0] = zr0; *(uint4*)&zb[4] = zr1;
            __nv_bfloat162 o[8];
            size_t eidx = (rowbase + it) * UNITS + n0 + ecb;
            #pragma unroll
            for (int c = 0; c < 8; c++)
                o[c] = __floats2bfloat162_rn(
                    tanhfast(s[2*c]     + __low2float(zb[c])  + sBias[ecb + 2*c]),
                    tanhfast(s[2*c + 1] + __high2float(zb[c]) + sBias[ecb + 2*c + 1]));
            __nv_bfloat16* dst = g_H + eidx;
            *(uint4*)dst       = *(uint4*)&o[0];
            *(uint4*)(dst + 8) = *(uint4*)&o[4];
        }

        const bool needBar = doRec && (hasZ || it < SEQ - 1);
        if (needBar) {
            tgt += 8;
            __syncthreads();          // all h stores done (and sC reads done)
            if (tid == 0) {
                __threadfence();
                atomicAdd(&g_arr[mg], 1u);   // arrive early; Z epilogue fills the wait
            }
        }

        if (doZ) {
            // Z^{l+1}_{it-1} tile -> g_Z (block-local; safe vs own reads)
            wmma::store_matrix_sync(&sC[(wm * 32) * LDSC + wn * 16],      accZ[0], LDSC, wmma::mem_row_major);
            wmma::store_matrix_sync(&sC[(wm * 32 + 16) * LDSC + wn * 16], accZ[1], LDSC, wmma::mem_row_major);
            __syncthreads();
            const float* s = &sC[erow * LDSC + ecb];
            __nv_bfloat162 o[8];
            #pragma unroll
            for (int c = 0; c < 8; c++)
                o[c] = __floats2bfloat162_rn(s[2*c], s[2*c + 1]);
            __nv_bfloat16* dst = g_Z + (rowbase + (it - 1)) * UNITS + n0 + ecb;
            *(uint4*)dst       = *(uint4*)&o[0];
            *(uint4*)(dst + 8) = *(uint4*)&o[4];
        }

        if (needBar) {
            if (tid == 0) {
                volatile unsigned int* p = &g_arr[mg];
                while (*p < tgt) { }
                __threadfence();
            }
            __syncthreads();
        }
    }
}

// ---------------- head ----------------
__global__ void head(const float* __restrict__ Wo, const float* __restrict__ bo,
                     float* __restrict__ out) {
    int gt = blockIdx.x * blockDim.x + threadIdx.x;
    int w = gt >> 5, lane = gt & 31;
    if (w >= BATCH) return;
    const __nv_bfloat16* h = g_H + ((size_t)w * SEQ + (SEQ - 1)) * UNITS;
    float s = 0.f;
    for (int k = lane; k < UNITS; k += 32)
        s += __bfloat162float(h[k]) * Wo[k];
    #pragma unroll
    for (int o = 16; o; o >>= 1) s += __shfl_xor_sync(0xffffffffu, s, o);
    if (lane == 0) out[w] = 1.f / (1.f + expf(-(s + bo[0])));
}

// ---------------- launch ----------------
extern "C" void kernel_launch(void* const* d_in, const int* in_sizes, int n_in,
                              void* d_out, int out_size) {
    const int*   tokens = (const int*)d_in[0];
    const float* emb    = (const float*)d_in[1];
    const float* Wm[4]  = {(const float*)d_in[2],  (const float*)d_in[5],
                           (const float*)d_in[8],  (const float*)d_in[11]};
    const float* Um[4]  = {(const float*)d_in[3],  (const float*)d_in[6],
                           (const float*)d_in[9],  (const float*)d_in[12]};
    const float* bm[4]  = {(const float*)d_in[4],  (const float*)d_in[7],
                           (const float*)d_in[10], (const float*)d_in[13]};
    const float* Wo = (const float*)d_in[14];
    const float* bo = (const float*)d_in[15];
    float* out = (float*)d_out;

    cudaFuncSetAttribute(gemm0,      cudaFuncAttributeMaxDynamicSharedMemorySize, BULK_SMEM);
    cudaFuncSetAttribute(scan_layer, cudaFuncAttributeMaxDynamicSharedMemorySize, SCAN_SMEM);

    void* barAddr = nullptr;
    cudaGetSymbolAddress(&barAddr, g_arr);
    cudaMemsetAsync(barAddr, 0, 16 * sizeof(unsigned int));

    embed_kernel<<<(int)(((size_t)BT * EMBP + 255) / 256), 256>>>(tokens, emb);

    dim3 pg(1024, 8);
    prep_all<<<pg, 256>>>(Wm[0], Wm[1], Wm[2], Wm[3], Um[0], Um[1], Um[2], Um[3]);

    dim3 gin(UNITS / GBN, BT / BM);     // (4, 1280)
    gemm0<<<gin, THREADS, BULK_SMEM>>>();

    for (int l = 0; l < 4; l++) {
        int hasZ = (l < 3) ? 1 : 0;
        scan_layer<<<NBLK, THREADS, SCAN_SMEM>>>(l, bm[l], hasZ, (unsigned)(l * SEQ * 8));
    }
    head<<<(BATCH * 32 + 255) / 256, 256>>>(Wo, bo, out);
}